// round 16
// baseline (speedup 1.0000x reference)
#include <cuda_runtime.h>
#include <mma.h>
#include <cstdint>

using namespace nvcuda;

// ---------------------------------------------------------------------------
// Problem constants
// ---------------------------------------------------------------------------
#define HDIM    128
#define MSGDIM  256
#define GDIM    384
#define MAXROWS 200192      // 200000 rounded up to a multiple of 128 (pad rows)

// Gate pre-activation scratch for the messages GEMM only (g_gh eliminated)
__device__ float g_gi[(size_t)MAXROWS * GDIM];   // X @ W_ih^T

// ---------------------------------------------------------------------------
// Pass-through copy (float4 grid-stride)
// ---------------------------------------------------------------------------
__global__ void copy_f4(const float4* __restrict__ src, float4* __restrict__ dst,
                        size_t n4) {
    size_t i = (size_t)blockIdx.x * blockDim.x + threadIdx.x;
    size_t stride = (size_t)gridDim.x * blockDim.x;
    for (; i < n4; i += stride) dst[i] = src[i];
}

__device__ __forceinline__ void cpa16(uint32_t smem_dst, const float* gsrc) {
    asm volatile("cp.async.cg.shared.global [%0], [%1], 16;"
                 :: "r"(smem_dst), "l"(gsrc));
}

#define LDA 36                                // 32 + 4 pad

// ---------------------------------------------------------------------------
// gemm1 (UNCHANGED from best-measured R13): g_gi = messages @ W_ih^T, K=256.
// CTA tile 128x128x32, 256 threads (8 warps 2x4, warp tile 64x32),
// cp.async double-buffered, raw fp32 bits into tf32 MMA (HW truncation).
// ---------------------------------------------------------------------------
static constexpr int G1_SMEM = 2 * 2 * 128 * LDA * 4;   // 73728 B

__global__ void __launch_bounds__(256, 2)
gemm1(const float* __restrict__ A, const float* __restrict__ W, int B) {
    extern __shared__ float sm[];
    float* As = sm;                     // [2][128][LDA]
    float* Ws = sm + 2 * 128 * LDA;     // [2][128][LDA]

    const int t  = threadIdx.x;
    const int rb = blockIdx.x * 128;
    const int cb = blockIdx.y * 128;

    const int lm = t >> 1;
    const int lk = (t & 1) * 16;

    int arow = rb + lm; if (arow > B - 1) arow = B - 1;
    const float* Ap = A + (size_t)arow * MSGDIM + lk;
    const float* Wp = W + (size_t)(cb + lm) * MSGDIM + lk;

    const uint32_t sA = (uint32_t)__cvta_generic_to_shared(As + lm * LDA + lk);
    const uint32_t sW = (uint32_t)__cvta_generic_to_shared(Ws + lm * LDA + lk);
    const uint32_t bufB = 128 * LDA * 4;

    const int wid = t >> 5;
    const int wm  = wid >> 2;   // 0..1
    const int wn  = wid & 3;    // 0..3

    wmma::fragment<wmma::accumulator, 16, 16, 8, float> acc[4][2];
    #pragma unroll
    for (int mf = 0; mf < 4; mf++)
        #pragma unroll
        for (int nf = 0; nf < 2; nf++)
            wmma::fill_fragment(acc[mf][nf], 0.0f);

    auto load_stage = [&](int s) {
        const uint32_t boff = (uint32_t)(s & 1) * bufB;
        const float* ap = Ap + s * 32;
        const float* wp = Wp + s * 32;
        #pragma unroll
        for (int q = 0; q < 4; q++) {
            cpa16(sA + boff + q * 16, ap + q * 4);
            cpa16(sW + boff + q * 16, wp + q * 4);
        }
        asm volatile("cp.async.commit_group;");
    };

    load_stage(0);

    for (int s = 0; s < 8; s++) {
        if (s + 1 < 8) {
            load_stage(s + 1);
            asm volatile("cp.async.wait_group 1;");
        } else {
            asm volatile("cp.async.wait_group 0;");
        }
        __syncthreads();

        const float* Ab = As + (s & 1) * 128 * LDA;
        const float* Wb = Ws + (s & 1) * 128 * LDA;

        #pragma unroll
        for (int ks = 0; ks < 4; ks++) {
            wmma::fragment<wmma::matrix_a, 16, 16, 8,
                           wmma::precision::tf32, wmma::row_major> af[4];
            wmma::fragment<wmma::matrix_b, 16, 16, 8,
                           wmma::precision::tf32, wmma::col_major> bf[2];
            #pragma unroll
            for (int mf = 0; mf < 4; mf++)
                wmma::load_matrix_sync(af[mf], Ab + (wm * 64 + mf * 16) * LDA + ks * 8, LDA);
            #pragma unroll
            for (int nf = 0; nf < 2; nf++)
                wmma::load_matrix_sync(bf[nf], Wb + (wn * 32 + nf * 16) * LDA + ks * 8, LDA);
            #pragma unroll
            for (int mf = 0; mf < 4; mf++)
                #pragma unroll
                for (int nf = 0; nf < 2; nf++)
                    wmma::mma_sync(acc[mf][nf], af[mf], bf[nf], acc[mf][nf]);
        }
        __syncthreads();
    }

    #pragma unroll
    for (int mf = 0; mf < 4; mf++) {
        const int row = rb + wm * 64 + mf * 16;
        #pragma unroll
        for (int nf = 0; nf < 2; nf++) {
            const int col = cb + wn * 32 + nf * 16;
            wmma::store_matrix_sync(g_gi + (size_t)row * GDIM + col,
                                    acc[mf][nf], GDIM, wmma::mem_row_major);
        }
    }
}

// ---------------------------------------------------------------------------
// gemm2 + epilogue fused: gh = gathered_h @ W_hh^T (K=128) computed for the
// FULL N=384 per CTA (128 rows), then GRU gates + scatter — no gh scratch.
// 512 threads, 16 warps 4x4, warp tile 32x96 (acc[2][6] = 96 regs).
// Accumulators dumped to smem in two 64-row passes (reusing the A/W region).
// ---------------------------------------------------------------------------
#define DLD 388
static constexpr int OFF_A2   = 0;          // [2][128][LDA] = 9216 floats
static constexpr int OFF_W2   = 9216;       // [2][384][LDA] = 27648 floats
static constexpr int OFF_NODE = 36864;      // 128 ints
static constexpr int OFF_TS   = 36992;      // 128 floats
static constexpr int OFF_BIH  = 37120;      // 384 floats
static constexpr int OFF_BHH  = 37504;      // 384 floats
static constexpr int G2_SMEM  = 37888 * 4;  // 151552 B (dump 64x388 reuses A/W)

__global__ void __launch_bounds__(512, 1)
gemm2_fused(const float* __restrict__ memory,
            const int*   __restrict__ ids,
            const float* __restrict__ ts,
            const float* __restrict__ W_hh,
            const float* __restrict__ b_ih,
            const float* __restrict__ b_hh,
            float* __restrict__ out_mem,
            float* __restrict__ out_lu,
            int B) {
    extern __shared__ float sm[];
    const int t  = threadIdx.x;
    const int rb = blockIdx.x * 128;

    // ---- prologue: node ids, timestamps, biases
    if (t < 128) {
        int r = rb + t; if (r > B - 1) r = B - 1;
        ((int*)(sm + OFF_NODE))[t] = ids[r];
        sm[OFF_TS + t] = ts[r];
    } else if (t < 512) {
        int j = t - 128;
        if (j < GDIM) sm[OFF_BIH + j] = b_ih[j];
    }
    if (t < GDIM) sm[OFF_BHH + t] = b_hh[t];
    __syncthreads();
    const int* s_node = (const int*)(sm + OFF_NODE);

    const int wid = t >> 5;
    const int wm  = wid >> 2;        // 0..3 -> rows wm*32
    const int wn  = wid & 3;         // 0..3 -> cols wn*96

    wmma::fragment<wmma::accumulator, 16, 16, 8, float> acc[2][6];
    #pragma unroll
    for (int mf = 0; mf < 2; mf++)
        #pragma unroll
        for (int nf = 0; nf < 6; nf++)
            wmma::fill_fragment(acc[mf][nf], 0.0f);

    const uint32_t smA = (uint32_t)__cvta_generic_to_shared(sm + OFF_A2);
    const uint32_t smW = (uint32_t)__cvta_generic_to_shared(sm + OFF_W2);

    auto load_stage = [&](int s) {
        const int buf = s & 1;
        const int k0  = s * 32;
        // A: 128 rows x 32 = 1024 float4, 2 per thread (gathered)
        #pragma unroll
        for (int u = 0; u < 2; u++) {
            int fi = u * 512 + t, row = fi >> 3, c4 = (fi & 7) * 4;
            int node = s_node[row];
            cpa16(smA + (buf * 128 * LDA + row * LDA + c4) * 4,
                  memory + (size_t)node * HDIM + k0 + c4);
        }
        // W: 384 rows x 32 = 3072 float4, 6 per thread
        #pragma unroll
        for (int u = 0; u < 6; u++) {
            int fi = u * 512 + t, wr = fi >> 3, wc = (fi & 7) * 4;
            cpa16(smW + (buf * 384 * LDA + wr * LDA + wc) * 4,
                  W_hh + (size_t)wr * HDIM + k0 + wc);
        }
        asm volatile("cp.async.commit_group;");
    };

    load_stage(0);
    for (int s = 0; s < 4; s++) {
        if (s + 1 < 4) {
            load_stage(s + 1);
            asm volatile("cp.async.wait_group 1;");
        } else {
            asm volatile("cp.async.wait_group 0;");
        }
        __syncthreads();

        const float* Ab = sm + OFF_A2 + (s & 1) * 128 * LDA + (wm * 32) * LDA;
        const float* Wb = sm + OFF_W2 + (s & 1) * 384 * LDA + (wn * 96) * LDA;
        #pragma unroll
        for (int ks = 0; ks < 4; ks++) {
            wmma::fragment<wmma::matrix_a, 16, 16, 8,
                           wmma::precision::tf32, wmma::row_major> af[2];
            #pragma unroll
            for (int mf = 0; mf < 2; mf++)
                wmma::load_matrix_sync(af[mf], Ab + mf * 16 * LDA + ks * 8, LDA);
            #pragma unroll
            for (int nf = 0; nf < 6; nf++) {
                wmma::fragment<wmma::matrix_b, 16, 16, 8,
                               wmma::precision::tf32, wmma::col_major> bf;
                wmma::load_matrix_sync(bf, Wb + nf * 16 * LDA + ks * 8, LDA);
                #pragma unroll
                for (int mf = 0; mf < 2; mf++)
                    wmma::mma_sync(acc[mf][nf], af[mf], bf, acc[mf][nf]);
            }
        }
        __syncthreads();
    }

    // ---- epilogue in two 64-row passes (dump reuses A/W smem region)
    float* dump = sm;                       // [64][DLD]
    const float* bih = sm + OFF_BIH;
    const float* bhh = sm + OFF_BHH;

    #pragma unroll 1
    for (int pass = 0; pass < 2; pass++) {
        if ((wm >> 1) == pass) {
            const int mrow = (wm & 1) * 32;
            #pragma unroll
            for (int mf = 0; mf < 2; mf++)
                #pragma unroll
                for (int nf = 0; nf < 6; nf++)
                    wmma::store_matrix_sync(dump + (mrow + mf * 16) * DLD + wn * 96 + nf * 16,
                                            acc[mf][nf], DLD, wmma::mem_row_major);
        }
        __syncthreads();

        // 64 rows x 128 h = 8192 elems, 16 per thread
        #pragma unroll
        for (int e = 0; e < 16; e++) {
            int idx  = e * 512 + t;
            int m    = idx >> 7, h = idx & 127;
            int lrow = pass * 64 + m;
            int brow = rb + lrow;
            int node = s_node[lrow];
            const float* gi = g_gi + (size_t)brow * GDIM;
            float rg = gi[h]       + bih[h]       + dump[m * DLD + h]       + bhh[h];
            float zg = gi[128 + h] + bih[128 + h] + dump[m * DLD + 128 + h] + bhh[128 + h];
            float ig = gi[256 + h] + bih[256 + h];
            float hg = dump[m * DLD + 256 + h] + bhh[256 + h];
            float r = 1.0f / (1.0f + expf(-rg));
            float z = 1.0f / (1.0f + expf(-zg));
            float n = tanhf(ig + r * hg);
            float hp = memory[(size_t)node * HDIM + h];
            if (brow < B)
                out_mem[(size_t)node * HDIM + h] = (1.0f - z) * n + z * hp;
        }
        if (t < 64) {
            int lrow = pass * 64 + t;
            if (rb + lrow < B) out_lu[s_node[lrow]] = sm[OFF_TS + lrow];
        }
        __syncthreads();
    }
}

// ---------------------------------------------------------------------------
// kernel_launch
// Inputs: 0 memory 1 last_update 2 ids 3 messages 4 ts 5 W_ih 6 W_hh 7 b_ih 8 b_hh
// Output: [memory' | last_update'] f32
// ---------------------------------------------------------------------------
extern "C" void kernel_launch(void* const* d_in, const int* in_sizes, int n_in,
                              void* d_out, int out_size) {
    const float* memory      = (const float*)d_in[0];
    const float* last_update = (const float*)d_in[1];
    const int*   ids         = (const int*)d_in[2];
    const float* messages    = (const float*)d_in[3];
    const float* ts          = (const float*)d_in[4];
    const float* W_ih        = (const float*)d_in[5];
    const float* W_hh        = (const float*)d_in[6];
    const float* b_ih        = (const float*)d_in[7];
    const float* b_hh        = (const float*)d_in[8];

    const int    B      = in_sizes[2];
    const size_t memN   = (size_t)in_sizes[0];
    const size_t nNodes = (size_t)in_sizes[1];

    float* out_mem = (float*)d_out;
    float* out_lu  = (float*)d_out + memN;

    cudaFuncSetAttribute(gemm1,
                         cudaFuncAttributeMaxDynamicSharedMemorySize, G1_SMEM);
    cudaFuncSetAttribute(gemm2_fused,
                         cudaFuncAttributeMaxDynamicSharedMemorySize, G2_SMEM);

    // Phase 0: pass-through copies (updated rows overwritten in phase 2)
    copy_f4<<<2960, 256>>>((const float4*)memory, (float4*)out_mem, memN / 4);
    copy_f4<<<256, 256>>>((const float4*)last_update, (float4*)out_lu, nNodes / 4);

    // Phase 1: gi = messages @ W_ih^T (R13-identical)
    dim3 g1((B + 127) / 128, GDIM / 128);
    gemm1<<<g1, 256, G1_SMEM>>>(messages, W_ih, B);

    // Phase 2: gh GEMM (full N=384 per CTA) + GRU gates + scatter, fused
    gemm2_fused<<<(B + 127) / 128, 512, G2_SMEM>>>(memory, ids, ts, W_hh,
                                                   b_ih, b_hh, out_mem, out_lu, B);
}

// round 17
// speedup vs baseline: 1.0760x; 1.0760x over previous
#include <cuda_runtime.h>
#include <mma.h>
#include <cstdint>

using namespace nvcuda;

// ---------------------------------------------------------------------------
// Problem constants
// ---------------------------------------------------------------------------
#define HDIM    128
#define MSGDIM  256
#define GDIM    384
#define MAXROWS 200192      // 200000 rounded up to a multiple of 128 (pad rows)

// Gate pre-activation scratch (device globals: no cudaMalloc allowed)
__device__ float g_gi[(size_t)MAXROWS * GDIM];   // X @ W_ih^T
__device__ float g_gh[(size_t)MAXROWS * GDIM];   // h @ W_hh^T

// ---------------------------------------------------------------------------
// Pass-through copy (float4 grid-stride)
// ---------------------------------------------------------------------------
__global__ void copy_f4(const float4* __restrict__ src, float4* __restrict__ dst,
                        size_t n4) {
    size_t i = (size_t)blockIdx.x * blockDim.x + threadIdx.x;
    size_t stride = (size_t)gridDim.x * blockDim.x;
    for (; i < n4; i += stride) dst[i] = src[i];
}

// ---------------------------------------------------------------------------
// wmma tf32 GEMM:  C[b, j] = sum_k A[row(b), k] * W[j, k]
// CTA tile 128x128x32, 256 threads (8 warps 2x4, warp tile 64x32).
// THREE-stage cp.async pipeline, ONE __syncthreads per K-chunk:
//   iter s:  wait(group s) ; sync ; prefetch chunk s+2 ; compute chunk s
// Buffer (s+2)%3 is never the buffer being read, so no trailing barrier.
// Raw fp32 bits are fed to the tf32 MMA (hardware truncation).
// ---------------------------------------------------------------------------
#define LDA 36                                  // 32 + 4 pad
static constexpr int STAGE_FLOATS = 128 * LDA;  // per-operand stage
static constexpr int SMEM_FLOATS  = 3 * 2 * STAGE_FLOATS;   // 3 stages, A+W
static constexpr int SMEM_BYTES   = SMEM_FLOATS * 4;        // 110592 B

template<int K>
__global__ void __launch_bounds__(256, 2)
gemm_wmma(const float* __restrict__ A, const int* __restrict__ ids,
          const float* __restrict__ W, int which, int B) {
    extern __shared__ float sm[];
    float* As = sm;                       // [3][128][LDA]
    float* Ws = sm + 3 * STAGE_FLOATS;    // [3][128][LDA]
    float* __restrict__ C = which ? g_gh : g_gi;

    const int t  = threadIdx.x;
    // grid: x = column tile (3), y = row tile  -> column-CTAs share A in L2
    const int cb = blockIdx.x * 128;
    const int rb = blockIdx.y * 128;

    // ---- global->smem mapping: 2 threads per row, 16 floats (4 float4) each
    const int lm = t >> 1;
    const int lk = (t & 1) * 16;

    int arow = rb + lm; if (arow > B - 1) arow = B - 1;   // clamp (pad rows)
    const int asrc = ids ? ids[arow] : arow;
    const float* Ap = A + (size_t)asrc * K + lk;
    const float* Wp = W + (size_t)(cb + lm) * K + lk;     // cb+lm <= 383

    const uint32_t sA = (uint32_t)__cvta_generic_to_shared(As + lm * LDA + lk);
    const uint32_t sW = (uint32_t)__cvta_generic_to_shared(Ws + lm * LDA + lk);
    const uint32_t bufB = STAGE_FLOATS * 4;

    // ---- warp tiling: 2x4 warps, each 64 rows x 32 cols
    const int wid = t >> 5;
    const int wm  = wid >> 2;   // 0..1
    const int wn  = wid & 3;    // 0..3

    wmma::fragment<wmma::accumulator, 16, 16, 8, float> acc[4][2];
    #pragma unroll
    for (int mf = 0; mf < 4; mf++)
        #pragma unroll
        for (int nf = 0; nf < 2; nf++)
            wmma::fill_fragment(acc[mf][nf], 0.0f);

    constexpr int S = K / 32;

    auto load_stage = [&](int s) {
        const uint32_t boff = (uint32_t)(s % 3) * bufB;
        const float* ap = Ap + s * 32;
        const float* wp = Wp + s * 32;
        #pragma unroll
        for (int q = 0; q < 4; q++) {
            asm volatile("cp.async.cg.shared.global [%0], [%1], 16;"
                         :: "r"(sA + boff + q * 16), "l"(ap + q * 4));
            asm volatile("cp.async.cg.shared.global [%0], [%1], 16;"
                         :: "r"(sW + boff + q * 16), "l"(wp + q * 4));
        }
        asm volatile("cp.async.commit_group;");
    };

    load_stage(0);
    load_stage(1);

    #pragma unroll 1
    for (int s = 0; s < S; s++) {
        if (s + 1 < S) {
            asm volatile("cp.async.wait_group 1;");   // group s complete
        } else {
            asm volatile("cp.async.wait_group 0;");
        }
        __syncthreads();            // single barrier per chunk

        if (s + 2 < S) load_stage(s + 2);   // safe: buffer (s+2)%3 != s%3

        const float* Ab = As + (s % 3) * STAGE_FLOATS;
        const float* Wb = Ws + (s % 3) * STAGE_FLOATS;

        #pragma unroll
        for (int ks = 0; ks < 4; ks++) {
            wmma::fragment<wmma::matrix_a, 16, 16, 8,
                           wmma::precision::tf32, wmma::row_major> af[4];
            wmma::fragment<wmma::matrix_b, 16, 16, 8,
                           wmma::precision::tf32, wmma::col_major> bf[2];
            #pragma unroll
            for (int mf = 0; mf < 4; mf++)
                wmma::load_matrix_sync(af[mf], Ab + (wm * 64 + mf * 16) * LDA + ks * 8, LDA);
            #pragma unroll
            for (int nf = 0; nf < 2; nf++)
                wmma::load_matrix_sync(bf[nf], Wb + (wn * 32 + nf * 16) * LDA + ks * 8, LDA);
            #pragma unroll
            for (int mf = 0; mf < 4; mf++)
                #pragma unroll
                for (int nf = 0; nf < 2; nf++)
                    wmma::mma_sync(acc[mf][nf], af[mf], bf[nf], acc[mf][nf]);
        }
    }

    // ---- store (pad rows land in scratch rows [B, MAXROWS), never read)
    #pragma unroll
    for (int mf = 0; mf < 4; mf++) {
        const int row = rb + wm * 64 + mf * 16;
        #pragma unroll
        for (int nf = 0; nf < 2; nf++) {
            const int col = cb + wn * 32 + nf * 16;
            wmma::store_matrix_sync(C + (size_t)row * GDIM + col,
                                    acc[mf][nf], GDIM, wmma::mem_row_major);
        }
    }
}

// ---------------------------------------------------------------------------
// GRU epilogue + scatter. One block per updated node, 128 threads (one per h).
// ---------------------------------------------------------------------------
__global__ void gru_epilogue(const float* __restrict__ memory,
                             const int* __restrict__ ids,
                             const float* __restrict__ ts,
                             const float* __restrict__ b_ih,
                             const float* __restrict__ b_hh,
                             float* __restrict__ out_mem,
                             float* __restrict__ out_lu,
                             int B) {
    int b = blockIdx.x;
    if (b >= B) return;
    int h = threadIdx.x;                 // 0..127
    int node = ids[b];

    const float* gi = g_gi + (size_t)b * GDIM;
    const float* gh = g_gh + (size_t)b * GDIM;

    float i_r = gi[h]       + b_ih[h];
    float i_z = gi[128 + h] + b_ih[128 + h];
    float i_n = gi[256 + h] + b_ih[256 + h];
    float h_r = gh[h]       + b_hh[h];
    float h_z = gh[128 + h] + b_hh[128 + h];
    float h_n = gh[256 + h] + b_hh[256 + h];

    float hprev = memory[(size_t)node * HDIM + h];

    float r = 1.0f / (1.0f + expf(-(i_r + h_r)));
    float z = 1.0f / (1.0f + expf(-(i_z + h_z)));
    float n = tanhf(i_n + r * h_n);
    float hnew = (1.0f - z) * n + z * hprev;

    out_mem[(size_t)node * HDIM + h] = hnew;
    if (h == 0) out_lu[node] = ts[b];
}

// ---------------------------------------------------------------------------
// kernel_launch
// Inputs: 0 memory 1 last_update 2 ids 3 messages 4 ts 5 W_ih 6 W_hh 7 b_ih 8 b_hh
// Output: [memory' | last_update'] f32
// ---------------------------------------------------------------------------
extern "C" void kernel_launch(void* const* d_in, const int* in_sizes, int n_in,
                              void* d_out, int out_size) {
    const float* memory      = (const float*)d_in[0];
    const float* last_update = (const float*)d_in[1];
    const int*   ids         = (const int*)d_in[2];
    const float* messages    = (const float*)d_in[3];
    const float* ts          = (const float*)d_in[4];
    const float* W_ih        = (const float*)d_in[5];
    const float* W_hh        = (const float*)d_in[6];
    const float* b_ih        = (const float*)d_in[7];
    const float* b_hh        = (const float*)d_in[8];

    const int    B      = in_sizes[2];
    const size_t memN   = (size_t)in_sizes[0];
    const size_t nNodes = (size_t)in_sizes[1];

    float* out_mem = (float*)d_out;
    float* out_lu  = (float*)d_out + memN;

    cudaFuncSetAttribute(gemm_wmma<MSGDIM>,
                         cudaFuncAttributeMaxDynamicSharedMemorySize, SMEM_BYTES);
    cudaFuncSetAttribute(gemm_wmma<HDIM>,
                         cudaFuncAttributeMaxDynamicSharedMemorySize, SMEM_BYTES);

    // Phase 0: pass-through copies (updated rows overwritten in phase 2)
    copy_f4<<<2960, 256>>>((const float4*)memory, (float4*)out_mem, memN / 4);
    copy_f4<<<256, 256>>>((const float4*)last_update, (float4*)out_lu, nNodes / 4);

    // Phase 1: gate pre-activations (grid = (coltile, rowtile) for A L2 reuse)
    dim3 ggrid(GDIM / 128, (B + 127) / 128);
    gemm_wmma<MSGDIM><<<ggrid, 256, SMEM_BYTES>>>(messages, nullptr, W_ih, 0, B);
    gemm_wmma<HDIM>  <<<ggrid, 256, SMEM_BYTES>>>(memory,   ids,     W_hh, 1, B);

    // Phase 2: GRU cell + scatter
    gru_epilogue<<<B, HDIM>>>(memory, ids, ts, b_ih, b_hh, out_mem, out_lu, B);
}